// round 17
// baseline (speedup 1.0000x reference)
#include <cuda_runtime.h>
#include <cuda_fp16.h>
#include <cstdint>

#define MAXN 50000
#define MAXE 800000
#define FIN 256
#define FH  64
#define FOUT 40
#define KSTEPS 10
#define SLOT 64          // padded-CSR slots per node (Poisson(16): P(deg>64) ~ 1e-20)

#define PACK2(out, lo, hi) asm("mov.b64 %0, {%1, %2};" : "=l"(out) : "f"(lo), "f"(hi))
#define UNPACK2(lo, hi, in) asm("mov.b64 {%0, %1}, %2;" : "=f"(lo), "=f"(hi) : "l"(in))
#define FMA2(d, a, b, c) asm("fma.rn.f32x2 %0, %1, %2, %3;" : "=l"(d) : "l"(a), "l"(b), "l"(c))

// ---------------- static device scratch ----------------
__device__ float   g_dinv[MAXN];
__device__ int     g_cursor[MAXN];       // memset to 0 each call; ends as raw degree
// padded CSR: node's edges at [node*SLOT, node*SLOT+deg)   {src, fp32 weight bits}
__device__ __align__(16) int2    g_csrp[MAXN * SLOT];
__device__ __align__(16) float   g_mlp1[MAXN * FH];     // ReLU intermediate (fp32)
// feature pairing: slot p of a node = features (2p, 2p+1); 128B rows, line-aligned
__device__ __align__(256) __half2 g_h0[MAXN * 32];
__device__ __align__(256) __half2 g_hA[MAXN * 32];
__device__ __align__(256) __half2 g_hB[MAXN * 32];

__device__ __forceinline__ int clampN(int v, int n) {
    v = v < 0 ? 0 : v;
    return v >= n ? n - 1 : v;
}

// ---------------- graph preprocessing (no hist pass: scatter counts) ----------
__global__ void scatter_kernel(const int* __restrict__ ei, int E, int n) {
    int e = blockIdx.x * blockDim.x + threadIdx.x;
    if (e < E) {
        int r = clampN(ei[e], n);
        int c = clampN(ei[E + e], n);
        int pos = atomicAdd(&g_cursor[c], 1);
        if (pos < SLOT) g_csrp[(c << 6) + pos] = make_int2(r, 0);
    }
}

__global__ void dinv_kernel(int n) {
    int i = blockIdx.x * blockDim.x + threadIdx.x;
    if (i < n) g_dinv[i] = rsqrtf((float)(g_cursor[i] + 1));  // + self loop
}

__global__ void wfill_kernel(int n) {
    int idx = blockIdx.x * blockDim.x + threadIdx.x;
    if (idx < n * SLOT) {
        int node = idx >> 6;
        int pos  = idx & 63;
        int deg  = min(g_cursor[node], SLOT);
        if (pos < deg) {
            int r = g_csrp[idx].x;
            float w = g_dinv[r] * g_dinv[node];
            g_csrp[idx].y = __float_as_int(w);
        }
    }
}

// ---------------- tiled GEMM: C[n,64] = A[n,KDIM] @ W[KDIM,64] + bias ----------
// Block 128x64, 256 threads, 8x4 micro-tile, BK=16, packed fma.rn.f32x2:
// A tile staged DUPLICATED as (v,v) float2 -> packed multiplier via LDS.128,
// W column pairs read packed. 16 FFMA2 + 5 LDS per kk (was 32 FFMA + 3 LDS).
template <int KDIM, int RELU, int OUTHALF>
__global__ void gemm128_kernel(const float* __restrict__ A,
                               const float* __restrict__ W,
                               const float* __restrict__ bias,
                               float* __restrict__ Cf, int n) {
    __shared__ float2 xs[16][132];  // [k][row] duplicated (v,v); 16B-aligned rows
    __shared__ float  ws[16][64];   // [k][col]
    int tid = threadIdx.x;
    int ty = tid >> 4, tx = tid & 15;
    int rowBase = blockIdx.x * 128;
    unsigned long long acc2[8][2] = {};   // packed (col0,col1),(col2,col3) per row

    for (int k0 = 0; k0 < KDIM; k0 += 16) {
        // A tile: thread loads 8 floats of one row, stores duplicated
        {
            int r  = tid >> 1;                  // 0..127
            int kq = (tid & 1) << 3;            // 0 or 8
            int grow = rowBase + r;
            float4 v0 = make_float4(0.f, 0.f, 0.f, 0.f);
            float4 v1 = make_float4(0.f, 0.f, 0.f, 0.f);
            if (grow < n) {
                const float* ap = &A[(size_t)grow * KDIM + k0 + kq];
                v0 = *(const float4*)ap;
                v1 = *(const float4*)(ap + 4);
            }
            xs[kq + 0][r] = make_float2(v0.x, v0.x);
            xs[kq + 1][r] = make_float2(v0.y, v0.y);
            xs[kq + 2][r] = make_float2(v0.z, v0.z);
            xs[kq + 3][r] = make_float2(v0.w, v0.w);
            xs[kq + 4][r] = make_float2(v1.x, v1.x);
            xs[kq + 5][r] = make_float2(v1.y, v1.y);
            xs[kq + 6][r] = make_float2(v1.z, v1.z);
            xs[kq + 7][r] = make_float2(v1.w, v1.w);
        }
        // W tile
        {
            int k  = tid >> 4;
            int cq = (tid & 15) << 2;
            *(float4*)&ws[k][cq] = *(const float4*)&W[(size_t)(k0 + k) * FH + cq];
        }
        __syncthreads();
        #pragma unroll
        for (int kk = 0; kk < 16; kk++) {
            const ulonglong2* ap = (const ulonglong2*)&xs[kk][ty << 3];
            ulonglong2 a01 = ap[0];
            ulonglong2 a23 = ap[1];
            ulonglong2 a45 = ap[2];
            ulonglong2 a67 = ap[3];
            ulonglong2 bv  = *(const ulonglong2*)&ws[kk][tx << 2];
            unsigned long long av[8] = {a01.x, a01.y, a23.x, a23.y,
                                        a45.x, a45.y, a67.x, a67.y};
            #pragma unroll
            for (int i = 0; i < 8; i++) {
                FMA2(acc2[i][0], av[i], bv.x, acc2[i][0]);
                FMA2(acc2[i][1], av[i], bv.y, acc2[i][1]);
            }
        }
        __syncthreads();
    }

    int c0 = tx << 2;
    float b0 = bias[c0 + 0], b1 = bias[c0 + 1];
    float b2 = bias[c0 + 2], b3 = bias[c0 + 3];
    #pragma unroll
    for (int i = 0; i < 8; i++) {
        int row = rowBase + (ty << 3) + i;
        if (row < n) {
            float r0, r1, r2, r3;
            UNPACK2(r0, r1, acc2[i][0]);
            UNPACK2(r2, r3, acc2[i][1]);
            r0 += b0; r1 += b1; r2 += b2; r3 += b3;
            if (RELU) {
                r0 = fmaxf(r0, 0.f); r1 = fmaxf(r1, 0.f);
                r2 = fmaxf(r2, 0.f); r3 = fmaxf(r3, 0.f);
            }
            if (!OUTHALF) {
                *(float4*)&Cf[(size_t)row * FH + c0] = make_float4(r0, r1, r2, r3);
            } else {
                __half2 p0 = __floats2half2_rn(r0, r1);
                __half2 p1 = __floats2half2_rn(r2, r3);
                int s = row * 32 + (c0 >> 1);
                g_hA[s] = p0;  g_hA[s + 1] = p1;
                g_h0[s] = p0;  g_h0[s + 1] = p1;
            }
        }
    }
}

// ---------------- APPNP step: warp/node, padded CSR, fp32 fmaf, unroll x4 ------
template <int SRC_A, int DECODE>
__global__ void prop_kernel(const float* __restrict__ Wf,
                            const float* __restrict__ bf,
                            float* __restrict__ out, int n) {
    int node = (blockIdx.x * blockDim.x + threadIdx.x) >> 5;
    int lane = threadIdx.x & 31;
    if (node >= n) return;
    const __half2* __restrict__ hin  = SRC_A ? g_hA : g_hB;
    __half2*       __restrict__ hout = SRC_A ? g_hB : g_hA;

    int deg = min(g_cursor[node], SLOT);
    int e   = node << 6;            // SLOT = 64
    int end = e + deg;

    float di = g_dinv[node];
    float wself = di * di;
    float2 hv = __half22float2(hin[node * 32 + lane]);
    float ax = wself * hv.x;
    float ay = wself * hv.y;

    for (; e + 4 <= end; e += 4) {
        int2 s0 = g_csrp[e + 0];         // uniform (broadcast) loads
        int2 s1 = g_csrp[e + 1];
        int2 s2 = g_csrp[e + 2];
        int2 s3 = g_csrp[e + 3];
        __half2 v0 = hin[s0.x * 32 + lane];  // 4 independent gathers in flight
        __half2 v1 = hin[s1.x * 32 + lane];
        __half2 v2 = hin[s2.x * 32 + lane];
        __half2 v3 = hin[s3.x * 32 + lane];
        float2 f0 = __half22float2(v0);
        float2 f1 = __half22float2(v1);
        float2 f2 = __half22float2(v2);
        float2 f3 = __half22float2(v3);
        float w0 = __int_as_float(s0.y);
        float w1 = __int_as_float(s1.y);
        float w2 = __int_as_float(s2.y);
        float w3 = __int_as_float(s3.y);
        ax = fmaf(w0, f0.x, ax);  ay = fmaf(w0, f0.y, ay);
        ax = fmaf(w1, f1.x, ax);  ay = fmaf(w1, f1.y, ay);
        ax = fmaf(w2, f2.x, ax);  ay = fmaf(w2, f2.y, ay);
        ax = fmaf(w3, f3.x, ax);  ay = fmaf(w3, f3.y, ay);
    }
    for (; e < end; e++) {
        int2 s = g_csrp[e];
        float2 f = __half22float2(hin[s.x * 32 + lane]);
        float w = __int_as_float(s.y);
        ax = fmaf(w, f.x, ax);
        ay = fmaf(w, f.y, ay);
    }

    float2 t = __half22float2(g_h0[node * 32 + lane]);
    float ox = 0.9f * ax + 0.1f * t.x;     // features (2l, 2l+1), fp32
    float oy = 0.9f * ay + 0.1f * t.y;

    if (!DECODE) {
        hout[node * 32 + lane] = __floats2half2_rn(ox, oy);
    } else {
        // fused decode: out[node] = h @ Wf + bf (h in registers, fp32)
        float acc0 = bf[lane];
        float acc1 = (lane < FOUT - 32) ? bf[lane + 32] : 0.0f;
        #pragma unroll
        for (int j = 0; j < 32; j++) {
            float hx = __shfl_sync(0xFFFFFFFFu, ox, j);   // feature 2j
            float hy = __shfl_sync(0xFFFFFFFFu, oy, j);   // feature 2j+1
            acc0 = fmaf(hx, Wf[(2 * j) * FOUT + lane], acc0);
            acc0 = fmaf(hy, Wf[(2 * j + 1) * FOUT + lane], acc0);
            if (lane < FOUT - 32) {
                acc1 = fmaf(hx, Wf[(2 * j) * FOUT + lane + 32], acc1);
                acc1 = fmaf(hy, Wf[(2 * j + 1) * FOUT + lane + 32], acc1);
            }
        }
        out[(size_t)node * FOUT + lane] = acc0;
        if (lane < FOUT - 32)
            out[(size_t)node * FOUT + lane + 32] = acc1;
    }
}

// ---------------- launch ----------------
extern "C" void kernel_launch(void* const* d_in, const int* in_sizes, int n_in,
                              void* d_out, int out_size) {
    const float* x  = (const float*)d_in[0];
    const int*   ei = (const int*)d_in[1];
    const float* W1 = (const float*)d_in[2];
    const float* b1 = (const float*)d_in[3];
    const float* W2 = (const float*)d_in[4];
    const float* b2 = (const float*)d_in[5];
    const float* Wf = (const float*)d_in[6];
    const float* bf = (const float*)d_in[7];
    float* out = (float*)d_out;

    int N = in_sizes[0] / FIN;
    int E = in_sizes[1] / 2;
    if (N > MAXN) N = MAXN;
    if (E > MAXE) E = MAXE;

    int tpb = 256;

    void* cur_addr = nullptr;
    void* mlp1_addr = nullptr;
    cudaGetSymbolAddress(&cur_addr, g_cursor);
    cudaGetSymbolAddress(&mlp1_addr, g_mlp1);
    cudaMemsetAsync(cur_addr, 0, (size_t)N * sizeof(int));

    scatter_kernel<<<(E + tpb - 1) / tpb, tpb>>>(ei, E, N);   // counts + src slots
    dinv_kernel<<<(N + tpb - 1) / tpb, tpb>>>(N);
    wfill_kernel<<<(N * SLOT + tpb - 1) / tpb, tpb>>>(N);     // weights into CSR

    // MLP encode as two tiled GEMMs (128-row blocks, packed f32x2)
    int gblocks = (N + 127) / 128;
    gemm128_kernel<FIN, 1, 0><<<gblocks, 256>>>(x, W1, b1, (float*)mlp1_addr, N);
    gemm128_kernel<FH, 0, 1><<<gblocks, 256>>>((const float*)mlp1_addr, W2, b2,
                                               nullptr, N);

    int wblocks = (N + 7) / 8;                 // 8 warps / 256-thread block
    // steps 0..8 normal; step 9 (reads B) fuses the decode
    for (int t = 0; t < KSTEPS - 1; t++) {
        if ((t & 1) == 0) prop_kernel<1, 0><<<wblocks, tpb>>>(Wf, bf, out, N);
        else              prop_kernel<0, 0><<<wblocks, tpb>>>(Wf, bf, out, N);
    }
    prop_kernel<0, 1><<<wblocks, tpb>>>(Wf, bf, out, N);
}